// round 13
// baseline (speedup 1.0000x reference)
#include <cuda_runtime.h>
#include <cuda_bf16.h>
#include <cstdint>

#define NN 50000
#define EE 800000
#define DD 512
#define NV4 (DD/4)
#define SLAB ((size_t)512 * 512)

// ---------------- static scratch (no allocations allowed) ----------------
__device__ float g_z[(size_t)4 * NN * DD];  // z planes (plane 0 reused for cat out)
// slots: 0=h 1=s1 2=s2 3=m1 4=m2 5=l1 6=l2 7=aggsum 8=aggmax
__device__ __nv_bfloat16 g_slh[(size_t)9 * NN * DD];
__device__ __nv_bfloat16 g_sll[(size_t)9 * NN * DD];
__device__ __nv_bfloat16 g_bh[44 * SLAB];   // B transposed hi (40 mixed slabs + cat)
__device__ __nv_bfloat16 g_bl[44 * SLAB];   // B transposed lo
__device__ float g_stats[11 * 4096];        // per-round col stats: [round][sum 2048 | sqr 2048]
__device__ int   g_deg[NN];
__device__ int   g_rowp[NN + 1];
__device__ int   g_cur[NN];
__device__ int   g_csrc[EE];
__device__ float g_invdeg[NN];

// ---------------- PTX helpers (sm_80-generic only) ----------------
__device__ __forceinline__ uint32_t smem_u32(const void* p) {
    uint32_t a;
    asm("{ .reg .u64 t; cvta.to.shared.u64 t, %1; cvt.u32.u64 %0, t; }" : "=r"(a) : "l"(p));
    return a;
}
__device__ __forceinline__ void cp_async16(uint32_t saddr, const void* gaddr, int sz) {
    asm volatile("cp.async.cg.shared.global [%0], [%1], 16, %2;"
                 :: "r"(saddr), "l"(gaddr), "r"(sz));
}
__device__ __forceinline__ void cp_commit() {
    asm volatile("cp.async.commit_group;");
}
template <int N>
__device__ __forceinline__ void cp_wait() {
    asm volatile("cp.async.wait_group %0;" :: "n"(N));
}
__device__ __forceinline__ void ldsm_x4(uint32_t& r0, uint32_t& r1, uint32_t& r2,
                                        uint32_t& r3, uint32_t addr) {
    asm volatile("ldmatrix.sync.aligned.m8n8.x4.shared.b16 {%0,%1,%2,%3}, [%4];"
                 : "=r"(r0), "=r"(r1), "=r"(r2), "=r"(r3) : "r"(addr));
}
__device__ __forceinline__ void mma_bf16(float* c, const uint32_t* a, const uint32_t* b) {
    asm volatile(
        "mma.sync.aligned.m16n8k16.row.col.f32.bf16.bf16.f32 "
        "{%0,%1,%2,%3}, {%4,%5,%6,%7}, {%8,%9}, {%0,%1,%2,%3};"
        : "+f"(c[0]), "+f"(c[1]), "+f"(c[2]), "+f"(c[3])
        : "r"(a[0]), "r"(a[1]), "r"(a[2]), "r"(a[3]), "r"(b[0]), "r"(b[1]));
}

__device__ __forceinline__ void split2(float x, float y, uint32_t& hi, uint32_t& lo) {
    __nv_bfloat162 h = __floats2bfloat162_rn(x, y);
    float rx = x - __bfloat162float(__low2bfloat16(h));
    float ry = y - __bfloat162float(__high2bfloat16(h));
    __nv_bfloat162 l = __floats2bfloat162_rn(rx, ry);
    hi = *(uint32_t*)&h;
    lo = *(uint32_t*)&l;
}
// reconstruct 2 floats from packed bf16x2 hi/lo
__device__ __forceinline__ float2 join2(uint32_t hi, uint32_t lo) {
    float2 H = __bfloat1622float2(*(__nv_bfloat162*)&hi);
    float2 L = __bfloat1622float2(*(__nv_bfloat162*)&lo);
    return make_float2(H.x + L.x, H.y + L.y);
}

// ---------------- CSR build ----------------
__global__ void k_count(const int* __restrict__ dst, int E) {
    int e = blockIdx.x * blockDim.x + threadIdx.x;
    if (e < E) atomicAdd(&g_deg[dst[e]], 1);
}

__global__ void k_scan(int M) {
    __shared__ int sh[1024];
    __shared__ int running;
    if (threadIdx.x == 0) running = 0;
    __syncthreads();
    for (int base = 0; base < M; base += 1024) {
        int i = base + threadIdx.x;
        int v = (i < M) ? g_deg[i] : 0;
        sh[threadIdx.x] = v;
        __syncthreads();
        for (int off = 1; off < 1024; off <<= 1) {
            int t = 0;
            if ((int)threadIdx.x >= off) t = sh[threadIdx.x - off];
            __syncthreads();
            sh[threadIdx.x] += t;
            __syncthreads();
        }
        int incl = sh[threadIdx.x];
        int excl = running + incl - v;
        if (i < M) {
            g_rowp[i] = excl;
            g_cur[i] = excl;
            g_invdeg[i] = 1.0f / (float)(v > 1 ? v : 1);
        }
        __syncthreads();
        if (threadIdx.x == 0) running += sh[1023];
        __syncthreads();
    }
    if (threadIdx.x == 0) g_rowp[M] = running;
}

__global__ void k_scatter(const int* __restrict__ src, const int* __restrict__ dst, int E) {
    int e = blockIdx.x * blockDim.x + threadIdx.x;
    if (e < E) {
        int d = dst[e];
        int p = atomicAdd(&g_cur[d], 1);
        g_csrc[p] = src[e];
    }
}

// -- aggregation: one block per node; reads slot hi/lo; writes slots 7 (sum), 8 (max) --
__global__ void k_aggregate(int slot, int M) {
    int nid = blockIdx.x;
    int t = threadIdx.x;
    int beg = g_rowp[nid], end = g_rowp[nid + 1];
    const uint2* XH = (const uint2*)(g_slh + (size_t)slot * NN * DD);
    const uint2* XL = (const uint2*)(g_sll + (size_t)slot * NN * DD);
    float4 s = make_float4(0.f, 0.f, 0.f, 0.f);
    float4 m = make_float4(-3.4e38f, -3.4e38f, -3.4e38f, -3.4e38f);
    for (int e = beg; e < end; e++) {
        int r = __ldg(&g_csrc[e]);
        uint2 hv = __ldg(XH + (size_t)r * 128 + t);
        uint2 lv = __ldg(XL + (size_t)r * 128 + t);
        float2 v01 = join2(hv.x, lv.x);
        float2 v23 = join2(hv.y, lv.y);
        s.x += v01.x; s.y += v01.y; s.z += v23.x; s.w += v23.y;
        m.x = fmaxf(m.x, v01.x); m.y = fmaxf(m.y, v01.y);
        m.z = fmaxf(m.z, v23.x); m.w = fmaxf(m.w, v23.y);
    }
    if (beg == end) m = make_float4(0.f, 0.f, 0.f, 0.f);
    size_t base = (size_t)nid * 256 + t * 2;  // in bf16x2 units
    uint32_t* sh1 = (uint32_t*)(g_slh + (size_t)7 * NN * DD);
    uint32_t* sl1 = (uint32_t*)(g_sll + (size_t)7 * NN * DD);
    uint32_t* sh2 = (uint32_t*)(g_slh + (size_t)8 * NN * DD);
    uint32_t* sl2 = (uint32_t*)(g_sll + (size_t)8 * NN * DD);
    uint32_t h, l;
    split2(s.x, s.y, h, l); sh1[base] = h; sl1[base] = l;
    split2(s.z, s.w, h, l); sh1[base + 1] = h; sl1[base + 1] = l;
    split2(m.x, m.y, h, l); sh2[base] = h; sl2[base] = l;
    split2(m.z, m.w, h, l); sh2[base + 1] = h; sl2[base + 1] = l;
}

// ---------------- split fp32 input into bf16 hi/lo slot ----------------
__global__ void k_split(const float* __restrict__ X, int slot, int M) {
    int idx = blockIdx.x * blockDim.x + threadIdx.x;
    int total = M * NV4;
    if (idx >= total) return;
    float4 v = ((const float4*)X)[idx];
    uint32_t* sh = (uint32_t*)(g_slh + (size_t)slot * NN * DD);
    uint32_t* sl = (uint32_t*)(g_sll + (size_t)slot * NN * DD);
    uint32_t h, l;
    split2(v.x, v.y, h, l); sh[idx * 2] = h; sl[idx * 2] = l;
    split2(v.z, v.w, h, l); sh[idx * 2 + 1] = h; sl[idx * 2 + 1] = l;
}

// ------ weight prep: transpose [K][N]->[N][K] + bf16 hi/lo split ------
__global__ void k_prep(const float* __restrict__ W, size_t dofs, int K, int N) {
    __shared__ float t[32][33];
    const float* Wp = W + (size_t)blockIdx.z * K * N;
    __nv_bfloat16* oh = g_bh + dofs + (size_t)blockIdx.z * K * N;
    __nv_bfloat16* ol = g_bl + dofs + (size_t)blockIdx.z * K * N;
    int k0 = blockIdx.x * 32;
    int n0 = blockIdx.y * 32;
    int tx = threadIdx.x & 31, ty = threadIdx.x >> 5;
    for (int r = ty; r < 32; r += 8)
        t[r][tx] = __ldg(Wp + (size_t)(k0 + r) * N + n0 + tx);
    __syncthreads();
    for (int r = ty; r < 32; r += 8) {
        float w = t[tx][r];
        __nv_bfloat16 hb = __float2bfloat16_rn(w);
        float lof = w - __bfloat162float(hb);
        size_t o = (size_t)(n0 + r) * K + k0 + tx;
        oh[o] = hb;
        ol[o] = __float2bfloat16_rn(lof);
    }
}

// ---------------- bf16x3 mma.sync GEMM (+ fused BN stats in epilogue) ----------------
// CTA 128x128 tile, 256 thr (8 warps: 4m x 2n), warp 32x64, BK=32, 2-stage, 2 CTAs/SM.
#define APLANE 10240
#define BPLANE 10240
#define STAGEB (2 * APLANE + 2 * BPLANE)   // 40960
#define SMEM_GEMM (2 * STAGEB)             // 81920

__global__ void __launch_bounds__(256, 2)
k_gemm_mma(const float* __restrict__ bias, int M, int mode, int aslot, size_t bofs,
           int round) {
    extern __shared__ char smem[];
    uint32_t sbase = smem_u32(smem);
    const int tid = threadIdx.x;
    const int wid = tid >> 5, lane = tid & 31;
    const int wm = wid & 3, wn = wid >> 2;
    const int plane = (mode == 0) ? (blockIdx.x >> 2) : 0;
    const int colBase = ((mode == 0) ? (blockIdx.x & 3) : blockIdx.x) * 128;
    const int rowBase = blockIdx.y * 128;

    const int K = (mode == 0) ? 512 : 2048;
    const int nStages = K / 32;
    const int bK = K;
    const size_t bOff = bofs + ((mode == 0) ? (size_t)plane * SLAB : 0);

    auto loadA = [&](int s) {
        int slot, kin;
        if (mode == 0) {
            slot = (plane == 0) ? aslot : ((plane == 3) ? 8 : 7);
            kin = s * 32;
        } else {
            slot = 3 + (s >> 4);
            kin = (s & 15) * 32;
        }
        const __nv_bfloat16* aH = g_slh + (size_t)slot * NN * DD;
        const __nv_bfloat16* aL = g_sll + (size_t)slot * NN * DD;
        uint32_t stg = sbase + (uint32_t)(s & 1) * STAGEB;
#pragma unroll
        for (int i = 0; i < 4; i++) {
            int idx = tid + 256 * i;
            int pl = idx >> 9, r = (idx >> 2) & 127, ch = idx & 3;
            int grow = rowBase + r;
            int gr = (grow < M) ? grow : (M - 1);
            const __nv_bfloat16* gp = (pl ? aL : aH) + (size_t)gr * 512 + kin + ch * 8;
            uint32_t dst = stg + pl * APLANE + r * 80 + ch * 16;
            cp_async16(dst, gp, (grow < M) ? 16 : 0);
        }
    };
    auto loadB = [&](int s) {
        int kin = s * 32;
        uint32_t stg = sbase + (uint32_t)(s & 1) * STAGEB + 2 * APLANE;
#pragma unroll
        for (int i = 0; i < 4; i++) {
            int idx = tid + 256 * i;
            int pl = idx >> 9, r = (idx >> 2) & 127, ch = idx & 3;
            const __nv_bfloat16* gp =
                (pl ? g_bl : g_bh) + bOff + (size_t)(colBase + r) * bK + kin + ch * 8;
            uint32_t dst = stg + pl * BPLANE + r * 80 + ch * 16;
            cp_async16(dst, gp, 16);
        }
    };

    float c[2][8][4];
#pragma unroll
    for (int mi = 0; mi < 2; mi++)
#pragma unroll
        for (int ni = 0; ni < 8; ni++)
#pragma unroll
            for (int j = 0; j < 4; j++) c[mi][ni][j] = 0.f;

    loadA(0); loadB(0); cp_commit();
    loadA(1); loadB(1); cp_commit();

    for (int s = 0; s < nStages; s++) {
        if (s + 1 < nStages) cp_wait<1>(); else cp_wait<0>();
        __syncthreads();
        uint32_t stg = sbase + (uint32_t)(s & 1) * STAGEB;
        uint32_t aHiB = stg, aLoB = stg + APLANE;
        uint32_t bHiB = stg + 2 * APLANE, bLoB = bHiB + BPLANE;
#pragma unroll
        for (int kc = 0; kc < 2; kc++) {
            uint32_t ah[2][4], al[2][4];
#pragma unroll
            for (int mi = 0; mi < 2; mi++) {
                int row = wm * 32 + mi * 16 + (lane & 15);
                uint32_t off = (uint32_t)row * 80 + kc * 32 + (lane >> 4) * 16;
                ldsm_x4(ah[mi][0], ah[mi][1], ah[mi][2], ah[mi][3], aHiB + off);
                ldsm_x4(al[mi][0], al[mi][1], al[mi][2], al[mi][3], aLoB + off);
            }
#pragma unroll
            for (int half = 0; half < 2; half++) {
                uint32_t bt[4][2], cl[4][2];
#pragma unroll
                for (int p = 0; p < 2; p++) {
                    int np = half * 2 + p;
                    int n = wn * 64 + np * 16 + ((lane >> 4) << 3) + (lane & 7);
                    uint32_t off = (uint32_t)n * 80 + kc * 32 + ((lane >> 3) & 1) * 16;
                    uint32_t h0, h1, h2, h3, l0, l1, l2, l3;
                    ldsm_x4(h0, h1, h2, h3, bHiB + off);
                    ldsm_x4(l0, l1, l2, l3, bLoB + off);
                    bt[2 * p][0] = h0; bt[2 * p][1] = h1;
                    bt[2 * p + 1][0] = h2; bt[2 * p + 1][1] = h3;
                    cl[2 * p][0] = l0; cl[2 * p][1] = l1;
                    cl[2 * p + 1][0] = l2; cl[2 * p + 1][1] = l3;
                }
#pragma unroll
                for (int t = 0; t < 4; t++)
#pragma unroll
                    for (int mi = 0; mi < 2; mi++)
                        mma_bf16(c[mi][half * 4 + t], ah[mi], bt[t]);
#pragma unroll
                for (int t = 0; t < 4; t++)
#pragma unroll
                    for (int mi = 0; mi < 2; mi++)
                        mma_bf16(c[mi][half * 4 + t], al[mi], bt[t]);
#pragma unroll
                for (int t = 0; t < 4; t++)
#pragma unroll
                    for (int mi = 0; mi < 2; mi++)
                        mma_bf16(c[mi][half * 4 + t], ah[mi], cl[t]);
            }
        }
        __syncthreads();
        if (s + 2 < nStages) { loadA(s + 2); loadB(s + 2); cp_commit(); }
    }

    // ---- epilogue: bias + rowscale + z write + fused column stats ----
    const float* bp = bias + ((mode == 0) ? plane * DD : 0);
    float* zbase = (mode == 0) ? (g_z + (size_t)plane * M * DD) : g_z;
    const int doScale = (mode == 0 && plane == 2);
    float* stats = g_stats + round * 4096;

    int r0A[2], r1A[2];
    float rs0A[2], rs1A[2];
#pragma unroll
    for (int mi = 0; mi < 2; mi++) {
        r0A[mi] = rowBase + wm * 32 + mi * 16 + (lane >> 2);
        r1A[mi] = r0A[mi] + 8;
        rs0A[mi] = (doScale && r0A[mi] < M) ? g_invdeg[r0A[mi]] : 1.f;
        rs1A[mi] = (doScale && r1A[mi] < M) ? g_invdeg[r1A[mi]] : 1.f;
    }
#pragma unroll
    for (int ni = 0; ni < 8; ni++) {
        int col = colBase + wn * 64 + ni * 8 + (lane & 3) * 2;
        float b0 = __ldg(bp + col), b1 = __ldg(bp + col + 1);
        float s0 = 0.f, s1 = 0.f, q0 = 0.f, q1 = 0.f;
#pragma unroll
        for (int mi = 0; mi < 2; mi++) {
            if (r0A[mi] < M) {
                float zx = fmaf(c[mi][ni][0], rs0A[mi], b0);
                float zy = fmaf(c[mi][ni][1], rs0A[mi], b1);
                *(float2*)(zbase + (size_t)r0A[mi] * DD + col) = make_float2(zx, zy);
                s0 += zx; q0 = fmaf(zx, zx, q0);
                s1 += zy; q1 = fmaf(zy, zy, q1);
            }
            if (r1A[mi] < M) {
                float zx = fmaf(c[mi][ni][2], rs1A[mi], b0);
                float zy = fmaf(c[mi][ni][3], rs1A[mi], b1);
                *(float2*)(zbase + (size_t)r1A[mi] * DD + col) = make_float2(zx, zy);
                s0 += zx; q0 = fmaf(zx, zx, q0);
                s1 += zy; q1 = fmaf(zy, zy, q1);
            }
        }
#pragma unroll
        for (int off = 4; off < 32; off <<= 1) {
            s0 += __shfl_xor_sync(0xffffffff, s0, off);
            s1 += __shfl_xor_sync(0xffffffff, s1, off);
            q0 += __shfl_xor_sync(0xffffffff, q0, off);
            q1 += __shfl_xor_sync(0xffffffff, q1, off);
        }
        if ((lane >> 2) == 0) {
            atomicAdd(&stats[plane * DD + col], s0);
            atomicAdd(&stats[plane * DD + col + 1], s1);
            atomicAdd(&stats[2048 + plane * DD + col], q0);
            atomicAdd(&stats[2048 + plane * DD + col + 1], q1);
        }
    }
}

// -- weighted relu combine over k (fused finalize; writes bf16 hi/lo slot only) --
__global__ void k_combine(const float* __restrict__ w, const float* __restrict__ gam,
                          const float* __restrict__ bet, int M, int round,
                          int acc, int slot) {
    __shared__ float s_sc[2048], s_sh[2048];
    int tid = threadIdx.x;
    float inv = 1.0f / (float)M;
    const float* st = g_stats + round * 4096;
    for (int i = tid; i < 2048; i += 256) {
        float mu = st[i] * inv;
        float var = st[2048 + i] * inv - mu * mu;
        float sc = rsqrtf(var + 1e-5f) * __ldg(gam + i);
        s_sc[i] = sc;
        s_sh[i] = __ldg(bet + i) - mu * sc;
    }
    __syncthreads();
    int idx = blockIdx.x * 256 + tid;
    if (idx >= M * NV4) return;
    int dc = (idx & (NV4 - 1)) * 4;
    uint32_t* shp = (uint32_t*)(g_slh + (size_t)slot * NN * DD);
    uint32_t* slp = (uint32_t*)(g_sll + (size_t)slot * NN * DD);
    float4 r = make_float4(0.f, 0.f, 0.f, 0.f);
    if (acc) {
        float2 a = join2(shp[idx * 2], slp[idx * 2]);
        float2 b = join2(shp[idx * 2 + 1], slp[idx * 2 + 1]);
        r = make_float4(a.x, a.y, b.x, b.y);
    }
#pragma unroll
    for (int k = 0; k < 4; k++) {
        float wk = __ldg(w + k);
        float4 v = __ldg((const float4*)g_z + (size_t)k * M * NV4 + idx);
        float4 sc = *(const float4*)&s_sc[k * DD + dc];
        float4 sh = *(const float4*)&s_sh[k * DD + dc];
        float e;
        e = fmaxf(fmaf(v.x, sc.x, sh.x), 0.f); r.x = fmaf(wk, e, r.x);
        e = fmaxf(fmaf(v.y, sc.y, sh.y), 0.f); r.y = fmaf(wk, e, r.y);
        e = fmaxf(fmaf(v.z, sc.z, sh.z), 0.f); r.z = fmaf(wk, e, r.z);
        e = fmaxf(fmaf(v.w, sc.w, sh.w), 0.f); r.w = fmaf(wk, e, r.w);
    }
    uint32_t h, l;
    split2(r.x, r.y, h, l); shp[idx * 2] = h; slp[idx * 2] = l;
    split2(r.z, r.w, h, l); shp[idx * 2 + 1] = h; slp[idx * 2 + 1] = l;
}

// ------- final residual + BN + relu (fused finalize; round 10, plane 0) -------
__global__ void k_final(const float* __restrict__ h, float* __restrict__ out,
                        const float* __restrict__ gam, const float* __restrict__ bet,
                        int M) {
    __shared__ float s_sc[512], s_sh[512];
    int tid = threadIdx.x;
    float inv = 1.0f / (float)M;
    const float* st = g_stats + 10 * 4096;
    for (int i = tid; i < 512; i += 256) {
        float mu = st[i] * inv;
        float var = st[2048 + i] * inv - mu * mu;
        float sc = rsqrtf(var + 1e-5f) * __ldg(gam + i);
        s_sc[i] = sc;
        s_sh[i] = __ldg(bet + i) - mu * sc;
    }
    __syncthreads();
    int idx = blockIdx.x * 256 + tid;
    if (idx >= M * NV4) return;
    int dc = (idx & (NV4 - 1)) * 4;
    float4 v = ((const float4*)g_z)[idx];
    float4 sc = *(const float4*)&s_sc[dc];
    float4 sh = *(const float4*)&s_sh[dc];
    float4 hv = ((const float4*)h)[idx];
    float4 o;
    o.x = hv.x + fmaxf(fmaf(v.x, sc.x, sh.x), 0.f);
    o.y = hv.y + fmaxf(fmaf(v.y, sc.y, sh.y), 0.f);
    o.z = hv.z + fmaxf(fmaf(v.z, sc.z, sh.z), 0.f);
    o.w = hv.w + fmaxf(fmaf(v.w, sc.w, sh.w), 0.f);
    ((float4*)out)[idx] = o;
}

// ---------------- host orchestration ----------------
static void run_mixed(int wslab, const float* b4, const float* g4, const float* be4,
                      const float* w4, int inSlot, int round, int acc, int outSlot,
                      int M) {
    k_gemm_mma<<<dim3(16, (M + 127) / 128, 1), 256, SMEM_GEMM>>>(
        b4, M, 0, inSlot, (size_t)wslab * SLAB, round);
    k_combine<<<(M * NV4 + 255) / 256, 256>>>(w4, g4, be4, M, round, acc, outSlot);
}

extern "C" void kernel_launch(void* const* d_in, const int* in_sizes, int n_in,
                              void* d_out, int out_size) {
    const float* h    = (const float*)d_in[0];
    const int*   src  = (const int*)d_in[1];
    const int*   dst  = (const int*)d_in[2];
    const float* wf   = (const float*)d_in[3];
    const float* wm   = (const float*)d_in[4];
    const float* wl   = (const float*)d_in[5];
    const float* pfW  = (const float*)d_in[6];
    const float* pfb  = (const float*)d_in[7];
    const float* pfg  = (const float*)d_in[8];
    const float* pfB  = (const float*)d_in[9];
    const float* pmW  = (const float*)d_in[10];
    const float* pmb  = (const float*)d_in[11];
    const float* pmg  = (const float*)d_in[12];
    const float* pmB  = (const float*)d_in[13];
    const float* plW  = (const float*)d_in[14];
    const float* plb  = (const float*)d_in[15];
    const float* plg  = (const float*)d_in[16];
    const float* plB  = (const float*)d_in[17];
    const float* catW = (const float*)d_in[18];
    const float* catb = (const float*)d_in[19];
    const float* bng  = (const float*)d_in[20];
    const float* bnb  = (const float*)d_in[21];

    int M = in_sizes[0] / DD;
    int E = in_sizes[1];
    float* out = (float*)d_out;

    cudaFuncSetAttribute(k_gemm_mma, cudaFuncAttributeMaxDynamicSharedMemorySize, SMEM_GEMM);

    void *degp, *statsp;
    cudaGetSymbolAddress(&degp, g_deg);
    cudaGetSymbolAddress(&statsp, g_stats);

    const size_t slabB = 4 * DD;
    const int nsp = (M * NV4 + 255) / 256;

    // ---- one-time zeroing + weight prep ----
    cudaMemsetAsync(statsp, 0, 11 * 4096 * sizeof(float));
    cudaMemsetAsync(degp, 0, M * sizeof(int));
    k_prep<<<dim3(16, 16, 12), 256>>>(pfW, 0, 512, 512);
    k_prep<<<dim3(16, 16, 8), 256>>>(pmW, 12 * SLAB, 512, 512);
    k_prep<<<dim3(16, 16, 20), 256>>>(plW, 20 * SLAB, 512, 512);
    k_prep<<<dim3(64, 16, 1), 256>>>(catW, 40 * SLAB, 2048, 512);

    // CSR build (shared by all aggregations this launch)
    k_count<<<(E + 255) / 256, 256>>>(dst, E);
    k_scan<<<1, 1024>>>(M);
    k_scatter<<<(E + 255) / 256, 256>>>(src, dst, E);

    // h into slot 0, then its aggregation into slots 7/8
    k_split<<<nsp, 256>>>(h, 0, M);
    k_aggregate<<<M, 128>>>(0, M);

    // first block: s1 = mixed(wf0, h); s2 = mixed(wf1, h) + mixed(wf2, s1)
    run_mixed(0,  pfb + 0 * slabB, pfg + 0 * slabB, pfB + 0 * slabB, wf + 0,
              0, 0, 0, 1, M);
    run_mixed(4,  pfb + 1 * slabB, pfg + 1 * slabB, pfB + 1 * slabB, wf + 4,
              0, 1, 0, 2, M);
    k_aggregate<<<M, 128>>>(1, M);
    run_mixed(8,  pfb + 2 * slabB, pfg + 2 * slabB, pfB + 2 * slabB, wf + 8,
              1, 2, 1, 2, M);
    // middle (agg(s1) still in slots 7/8): m1 = mixed(wm0, s1)
    run_mixed(12, pmb + 0 * slabB, pmg + 0 * slabB, pmB + 0 * slabB, wm + 0,
              1, 3, 0, 3, M);
    k_aggregate<<<M, 128>>>(2, M);
    run_mixed(16, pmb + 1 * slabB, pmg + 1 * slabB, pmB + 1 * slabB, wm + 4,
              2, 4, 0, 4, M);
    // last block: l1 = mixed(wl0,m1)+mixed(wl1,m2); l2 = mixed(wl2,m1)+mixed(wl3,m2)+mixed(wl4,l1)
    k_aggregate<<<M, 128>>>(3, M);
    run_mixed(20, plb + 0 * slabB, plg + 0 * slabB, plB + 0 * slabB, wl + 0,
              3, 5, 0, 5, M);
    run_mixed(28, plb + 2 * slabB, plg + 2 * slabB, plB + 2 * slabB, wl + 8,
              3, 6, 0, 6, M);
    k_aggregate<<<M, 128>>>(4, M);
    run_mixed(24, plb + 1 * slabB, plg + 1 * slabB, plB + 1 * slabB, wl + 4,
              4, 7, 1, 5, M);
    run_mixed(32, plb + 3 * slabB, plg + 3 * slabB, plB + 3 * slabB, wl + 12,
              4, 8, 1, 6, M);
    k_aggregate<<<M, 128>>>(5, M);
    run_mixed(36, plb + 4 * slabB, plg + 4 * slabB, plB + 4 * slabB, wl + 16,
              5, 9, 1, 6, M);

    // cat GEMM (round 10) + fused batchnorm + relu + residual
    k_gemm_mma<<<dim3(4, (M + 127) / 128, 1), 256, SMEM_GEMM>>>(
        catb, M, 1, 0, (size_t)40 * SLAB, 10);
    k_final<<<nsp, 256>>>(h, out, bng, bnb, M);
}